// round 15
// baseline (speedup 1.0000x reference)
#include <cuda_runtime.h>
#include <cuda_fp16.h>
#include <math.h>
#include <stdint.h>

#define NB    8
#define NC    256
#define HID   512
#define NPIX  4096
#define NHEAD 8
#define DHEAD 64
#define NCHUNK 8
#define TLD   260                    // 256 data cols + es at 256 + pad
#define TBH   (DHEAD * TLD)          // 16640

// ---------------- scratch ----------------
__device__ __align__(256) __half g_kh[NB * HID * NPIX];       // exp(k), 33.5 MB
__device__ __align__(256) __half g_wkh[HID * NC];
__device__ __align__(256) __half g_wqh[HID * NC];
__device__ __align__(256) __half g_wwh[NHEAD * NC * NC];      // WW[h] = Wo_h @ Wv_h, half
__device__ __align__(256) float g_Tpart[NCHUNK * NB * NHEAD * TBH];  // 34 MB
__device__ __align__(256) __half g_Tn[NB * NHEAD * DHEAD * NC];      // normalized T, half
__device__ __align__(256) float g_fold[NB * NC * HID];
__device__ __align__(256) float g_comb[NB * NC * NC];

// ---------------- helpers ----------------
__device__ __forceinline__ void mma_f16(float* d, const uint32_t* a, const uint32_t* b) {
    asm volatile(
        "mma.sync.aligned.m16n8k16.row.col.f32.f16.f16.f32 "
        "{%0,%1,%2,%3}, {%4,%5,%6,%7}, {%8,%9}, {%0,%1,%2,%3};"
        : "+f"(d[0]), "+f"(d[1]), "+f"(d[2]), "+f"(d[3])
        : "r"(a[0]), "r"(a[1]), "r"(a[2]), "r"(a[3]), "r"(b[0]), "r"(b[1]));
}

// ---------------- pack weights to half: Wk, Wq ----------------
__global__ void pack_w(const float* __restrict__ Wk, const float* __restrict__ Wq,
                       __half* __restrict__ Wkh, __half* __restrict__ Wqh)
{
    const int i = blockIdx.x * 256 + threadIdx.x;
    Wkh[i] = __float2half_rn(Wk[i]);
    Wqh[i] = __float2half_rn(Wq[i]);
}

// ---------------- WW[h][o][c] = sum_e Wo[o][h*64+e] * Wv[h*64+e][c] ----------------
__global__ void ww_kernel(const float* __restrict__ Wo, const float* __restrict__ Wv,
                          __half* __restrict__ WWh)
{
    const int h = blockIdx.x;
    const int ob = blockIdx.y;           // 16 o-rows per block
    __shared__ float wo_s[16][64];

    const int tid = threadIdx.x;
    for (int i = tid; i < 1024; i += 256) {
        const int o = i >> 6, e = i & 63;
        wo_s[o][e] = Wo[(size_t)(ob * 16 + o) * HID + h * 64 + e];
    }
    __syncthreads();

    const int c = tid;
    #pragma unroll 1
    for (int o = 0; o < 16; o++) {
        float s = 0.0f;
        #pragma unroll
        for (int e = 0; e < 64; e++)
            s += wo_s[o][e] * Wv[(size_t)(h * 64 + e) * NC + c];
        WWh[(size_t)h * NC * NC + (size_t)(ob * 16 + o) * NC + c] = __float2half_rn(s);
    }
}

// ---------------- fp16 mma GEMM (R8-proven), MODE 1 => half C with exp ----------------
template<int AHALF, int BHALF, int MODE>
__global__ __launch_bounds__(256, 2)
void mma_gemm_t(const void* __restrict__ Av, long sA, int lda,
                const void* __restrict__ Bv, long sB, int ldb,
                void* __restrict__ Cv, long sC, int ldc,
                const float* __restrict__ bias, int K, float alpha)
{
    __shared__ uint32_t As32[2][128][20];
    __shared__ uint32_t Bs32[2][16][136];

    const int bb = blockIdx.z;
    const float*  Af = (const float*)Av + (AHALF ? 0 : (size_t)bb * sA);
    const __half* Ah = (const __half*)Av + (AHALF ? (size_t)bb * sA : 0);
    const float*  Bf = (const float*)Bv + (BHALF ? 0 : (size_t)bb * sB);
    const __half* Bh = (const __half*)Bv + (BHALF ? (size_t)bb * sB : 0);

    const int tid = threadIdx.x;
    const int wid = tid >> 5, lid = tid & 31;
    const int g = lid >> 2, t = lid & 3;
    const int wm = (wid >> 2) * 64, wn = (wid & 3) * 32;
    const int m0 = blockIdx.y * 128, n0 = blockIdx.x * 128;

    const int am = tid >> 1;
    const int as = tid & 1;
    const int bk = tid >> 3;
    const int bn8 = (tid & 7) * 16;

    float acc[4][4][4];
    #pragma unroll
    for (int i = 0; i < 4; i++)
        #pragma unroll
        for (int j = 0; j < 4; j++)
            #pragma unroll
            for (int q = 0; q < 4; q++) acc[i][j][q] = 0.0f;

    const int KT = K >> 5;

    float4 aRf[4];
    uint4  aRh0, aRh1;
    float4 bRf[4];
    uint4  bRh0, bRh1;

    auto loadA = [&](int k0) {
        if (AHALF) {
            const __half* ap = Ah + (size_t)(m0 + am) * lda + k0 + as * 16;
            aRh0 = *(const uint4*)(ap);
            aRh1 = *(const uint4*)(ap + 8);
        } else {
            const float* ap = Af + (size_t)(m0 + am) * lda + k0;
            #pragma unroll
            for (int p = 0; p < 4; p++)
                aRf[p] = *(const float4*)(ap + (as + 2 * p) * 4);
        }
    };
    auto loadB = [&](int k0) {
        if (BHALF) {
            const __half* bp = Bh + (size_t)(k0 + bk) * ldb + n0 + bn8;
            bRh0 = *(const uint4*)(bp);
            bRh1 = *(const uint4*)(bp + 8);
        } else {
            const float* bp = Bf + (size_t)(k0 + bk) * ldb + n0 + bn8;
            #pragma unroll
            for (int p = 0; p < 4; p++)
                bRf[p] = *(const float4*)(bp + 4 * p);
        }
    };
    auto storeA = [&](int buf) {
        if (AHALF) {
            const int k2 = as * 8;
            As32[buf][am][k2 + 0] = aRh0.x; As32[buf][am][k2 + 1] = aRh0.y;
            As32[buf][am][k2 + 2] = aRh0.z; As32[buf][am][k2 + 3] = aRh0.w;
            As32[buf][am][k2 + 4] = aRh1.x; As32[buf][am][k2 + 5] = aRh1.y;
            As32[buf][am][k2 + 6] = aRh1.z; As32[buf][am][k2 + 7] = aRh1.w;
        } else {
            #pragma unroll
            for (int p = 0; p < 4; p++) {
                const int k2 = (as + 2 * p) * 2;
                __half2 h0 = __floats2half2_rn(aRf[p].x, aRf[p].y);
                __half2 h1 = __floats2half2_rn(aRf[p].z, aRf[p].w);
                As32[buf][am][k2 + 0] = *(uint32_t*)&h0;
                As32[buf][am][k2 + 1] = *(uint32_t*)&h1;
            }
        }
    };
    auto storeB = [&](int buf) {
        __half* bsh = (__half*)&Bs32[buf][0][0];
        const int base = (bk >> 1) * 272 + (bk & 1);
        if (BHALF) {
            const uint32_t w[8] = {bRh0.x, bRh0.y, bRh0.z, bRh0.w, bRh1.x, bRh1.y, bRh1.z, bRh1.w};
            #pragma unroll
            for (int q = 0; q < 8; q++) {
                __half2 h = *(__half2*)&w[q];
                bsh[base + 2 * (bn8 + 2 * q + 0)] = __low2half(h);
                bsh[base + 2 * (bn8 + 2 * q + 1)] = __high2half(h);
            }
        } else {
            #pragma unroll
            for (int p = 0; p < 4; p++) {
                const int nf = bn8 + 4 * p;
                bsh[base + 2 * (nf + 0)] = __float2half_rn(bRf[p].x);
                bsh[base + 2 * (nf + 1)] = __float2half_rn(bRf[p].y);
                bsh[base + 2 * (nf + 2)] = __float2half_rn(bRf[p].z);
                bsh[base + 2 * (nf + 3)] = __float2half_rn(bRf[p].w);
            }
        }
    };

    loadA(0);
    loadB(0);
    storeA(0);
    storeB(0);
    __syncthreads();

    for (int kt = 0; kt < KT; kt++) {
        const int cur = kt & 1;
        const int nxt = cur ^ 1;
        const bool more = (kt + 1 < KT);

        if (more) {
            loadA((kt + 1) << 5);
            loadB((kt + 1) << 5);
        }

        #pragma unroll
        for (int ks = 0; ks < 2; ks++) {
            const int kk2 = ks * 8;
            uint32_t af[4][4], bf[4][2];
            #pragma unroll
            for (int i = 0; i < 4; i++) {
                const int r = wm + i * 16 + g;
                af[i][0] = As32[cur][r][kk2 + t];
                af[i][1] = As32[cur][r + 8][kk2 + t];
                af[i][2] = As32[cur][r][kk2 + t + 4];
                af[i][3] = As32[cur][r + 8][kk2 + t + 4];
            }
            #pragma unroll
            for (int j = 0; j < 4; j++) {
                const int c = wn + j * 8 + g;
                bf[j][0] = Bs32[cur][kk2 + t][c];
                bf[j][1] = Bs32[cur][kk2 + t + 4][c];
            }
            #pragma unroll
            for (int i = 0; i < 4; i++)
                #pragma unroll
                for (int j = 0; j < 4; j++)
                    mma_f16(acc[i][j], af[i], bf[j]);
        }

        if (more) {
            storeA(nxt);
            storeB(nxt);
        }
        __syncthreads();
    }

    if (MODE == 0) {
        float* C = (float*)Cv + (size_t)bb * sC;
        #pragma unroll
        for (int i = 0; i < 4; i++) {
            const int r0 = m0 + wm + i * 16 + g;
            const int r1 = r0 + 8;
            const float bi0 = bias ? bias[r0] : 0.0f;
            const float bi1 = bias ? bias[r1] : 0.0f;
            #pragma unroll
            for (int j = 0; j < 4; j++) {
                const int col = n0 + wn + j * 8 + 2 * t;
                float2 o0 = make_float2(acc[i][j][0] * alpha + bi0, acc[i][j][1] * alpha + bi0);
                float2 o1 = make_float2(acc[i][j][2] * alpha + bi1, acc[i][j][3] * alpha + bi1);
                *(float2*)(C + (size_t)r0 * ldc + col) = o0;
                *(float2*)(C + (size_t)r1 * ldc + col) = o1;
            }
        }
    } else {
        __half* C = (__half*)Cv + (size_t)bb * sC;
        #pragma unroll
        for (int i = 0; i < 4; i++) {
            const int r0 = m0 + wm + i * 16 + g;
            const int r1 = r0 + 8;
            #pragma unroll
            for (int j = 0; j < 4; j++) {
                const int col = n0 + wn + j * 8 + 2 * t;
                float4 v = make_float4(expf(acc[i][j][0]), expf(acc[i][j][1]),
                                       expf(acc[i][j][2]), expf(acc[i][j][3]));
                *(__half2*)(C + (size_t)r0 * ldc + col) = __floats2half2_rn(v.x, v.y);
                *(__half2*)(C + (size_t)r1 * ldc + col) = __floats2half2_rn(v.z, v.w);
            }
        }
    }
}

// ---------------- T partial: T[d][c] = sum_m expk[d,m]*cin[c,m], split over m + c ----------------
// grid (64 bh, NCHUNK, 2 c-halves). es row-sums written by c-half 0 at col 256.
__global__ __launch_bounds__(256)
void t_partial_kernel(const __half* __restrict__ Kh, const float* __restrict__ cin,
                      float* __restrict__ part)
{
    const int bh = blockIdx.x;
    const int ch = blockIdx.y;
    const int nh = blockIdx.z;
    const int b = bh >> 3, h = bh & 7;
    const __half* kp = Kh + (size_t)b * HID * NPIX + (size_t)(h * 64) * NPIX;
    const float* bp0 = cin + (size_t)b * NC * NPIX + (size_t)(nh * 128) * NPIX;

    __shared__ uint32_t As32[64][20];    // expk [d][m2]
    __shared__ uint32_t Bs32[128][20];   // cin->half [c][m2]

    const int tid = threadIdx.x;
    const int wid = tid >> 5, lid = tid & 31;
    const int g = lid >> 2, t = lid & 3;
    const int wm = (wid & 3) * 16;       // d group
    const int wn = (wid >> 2) * 64;      // c offset (0 or 64) within this 128-half

    const int d  = tid >> 2;
    const int m8 = (tid & 3) << 3;
    const int w0 = m8 >> 1;
    const int cr  = tid >> 1;            // B row 0..127
    const int m16 = (tid & 1) * 16;

    float acc[8][4];
    #pragma unroll
    for (int j = 0; j < 8; j++)
        #pragma unroll
        for (int q = 0; q < 4; q++) acc[j][q] = 0.0f;

    float es = 0.0f;
    const int mbeg = ch * (NPIX / NCHUNK);
    const int mend = mbeg + (NPIX / NCHUNK);

    for (int m0 = mbeg; m0 < mend; m0 += 32) {
        uint4 ka = *(const uint4*)(kp + (size_t)d * NPIX + m0 + m8);
        As32[d][w0 + 0] = ka.x; As32[d][w0 + 1] = ka.y;
        As32[d][w0 + 2] = ka.z; As32[d][w0 + 3] = ka.w;
        float2 f0 = __half22float2(*(__half2*)&ka.x);
        float2 f1 = __half22float2(*(__half2*)&ka.y);
        float2 f2 = __half22float2(*(__half2*)&ka.z);
        float2 f3 = __half22float2(*(__half2*)&ka.w);
        es += (f0.x + f0.y) + (f1.x + f1.y) + ((f2.x + f2.y) + (f3.x + f3.y));

        const float* bp = bp0 + (size_t)cr * NPIX + m0 + m16;
        #pragma unroll
        for (int p = 0; p < 4; p++) {
            float4 v = *(const float4*)(bp + 4 * p);
            __half2 h0 = __floats2half2_rn(v.x, v.y);
            __half2 h1 = __floats2half2_rn(v.z, v.w);
            Bs32[cr][(tid & 1) * 8 + 2 * p + 0] = *(uint32_t*)&h0;
            Bs32[cr][(tid & 1) * 8 + 2 * p + 1] = *(uint32_t*)&h1;
        }
        __syncthreads();

        #pragma unroll
        for (int ks = 0; ks < 2; ks++) {
            const int kk2 = ks * 8;
            uint32_t af[4], bf[8][2];
            af[0] = As32[wm + g][kk2 + t];
            af[1] = As32[wm + g + 8][kk2 + t];
            af[2] = As32[wm + g][kk2 + t + 4];
            af[3] = As32[wm + g + 8][kk2 + t + 4];
            #pragma unroll
            for (int j = 0; j < 8; j++) {
                const int c = wn + j * 8 + g;
                bf[j][0] = Bs32[c][kk2 + t];
                bf[j][1] = Bs32[c][kk2 + t + 4];
            }
            #pragma unroll
            for (int j = 0; j < 8; j++)
                mma_f16(acc[j], af, bf[j]);
        }
        __syncthreads();
    }

    float* cp = part + ((size_t)ch * 64 + bh) * TBH;
    const int r0 = wm + g, r1 = wm + g + 8;
    #pragma unroll
    for (int j = 0; j < 8; j++) {
        const int c = nh * 128 + wn + j * 8 + 2 * t;
        cp[r0 * TLD + c]     = acc[j][0];
        cp[r0 * TLD + c + 1] = acc[j][1];
        cp[r1 * TLD + c]     = acc[j][2];
        cp[r1 * TLD + c + 1] = acc[j][3];
    }

    if (nh == 0) {
        es += __shfl_xor_sync(0xffffffffu, es, 1);
        es += __shfl_xor_sync(0xffffffffu, es, 2);
        if ((tid & 3) == 0) cp[d * TLD + 256] = es;
    }
}

// ---------------- reduce T partials + normalize -> Tn (half) ----------------
__global__ void reduce_t_kernel(const float* __restrict__ part, __half* __restrict__ Tn)
{
    const int bh = blockIdx.x;
    const int tid = threadIdx.x;

    __shared__ float Sd[64];
    if (tid < 64) {
        float s = 0.0f;
        #pragma unroll
        for (int ch = 0; ch < NCHUNK; ch++)
            s += part[((size_t)ch * 64 + bh) * TBH + tid * TLD + 256];
        Sd[tid] = 1.0f / s;
    }
    __syncthreads();

    uint2* outp = (uint2*)(Tn + (size_t)bh * DHEAD * NC);
    #pragma unroll 1
    for (int it = 0; it < 16; it++) {
        const int slot = it * 256 + tid;            // 4096 float4-slots
        const int dd = slot >> 6, c4 = (slot & 63) << 2;
        float4 s = make_float4(0.f, 0.f, 0.f, 0.f);
        #pragma unroll
        for (int ch = 0; ch < NCHUNK; ch++) {
            float4 p = *(const float4*)(part + ((size_t)ch * 64 + bh) * TBH + dd * TLD + c4);
            s.x += p.x; s.y += p.y; s.z += p.z; s.w += p.w;
        }
        const float iv = Sd[dd];
        __half2 h0 = __floats2half2_rn(s.x * iv, s.y * iv);
        __half2 h1 = __floats2half2_rn(s.z * iv, s.w * iv);
        uint2 u;
        u.x = *(uint32_t*)&h0;
        u.y = *(uint32_t*)&h1;
        outp[slot] = u;
    }
}

// ---------------- foldg: fold[b][o][h*64+d] = sum_c WW[h][o][c] * Tn[bh][d][c] ----------------
// grid (64 bh, 2 o-halves). NT fp16 mma, block 128(o) x 64(d), K=256.
__global__ __launch_bounds__(256)
void foldg_kernel(const __half* __restrict__ WWh, const __half* __restrict__ Tn,
                  float* __restrict__ fold)
{
    const int bh = blockIdx.x;
    const int ob = blockIdx.y;
    const int b = bh >> 3, h = bh & 7;
    const __half* A = WWh + (size_t)h * NC * NC + (size_t)ob * 128 * NC;
    const __half* B = Tn + (size_t)bh * DHEAD * NC;

    __shared__ uint32_t As32[128][20];
    __shared__ uint32_t Bs32[64][20];

    const int tid = threadIdx.x;
    const int wid = tid >> 5, lid = tid & 31;
    const int g = lid >> 2, t = lid & 3;
    const int wm = wid * 16;             // o group

    const int ar = tid >> 1, ac16 = (tid & 1) * 16;
    const int br = tid >> 2, bm8 = (tid & 3) << 3;

    float acc[8][4];
    #pragma unroll
    for (int j = 0; j < 8; j++)
        #pragma unroll
        for (int q = 0; q < 4; q++) acc[j][q] = 0.0f;

    for (int k0 = 0; k0 < NC; k0 += 32) {
        uint4 a0 = *(const uint4*)(A + (size_t)ar * NC + k0 + ac16);
        uint4 a1 = *(const uint4*)(A + (size_t)ar * NC + k0 + ac16 + 8);
        const int aw = (tid & 1) * 8;
        As32[ar][aw + 0] = a0.x; As32[ar][aw + 1] = a0.y;
        As32[ar][aw + 2] = a0.z; As32[ar][aw + 3] = a0.w;
        As32[ar][aw + 4] = a1.x; As32[ar][aw + 5] = a1.y;
        As32[ar][aw + 6] = a1.z; As32[ar][aw + 7] = a1.w;
        uint4 bv = *(const uint4*)(B + (size_t)br * NC + k0 + bm8);
        const int bw = bm8 >> 1;
        Bs32[br][bw + 0] = bv.x; Bs32[br][bw + 1] = bv.y;
        Bs32[br][bw + 2] = bv.z; Bs32[br][bw + 3] = bv.w;
        __syncthreads();

        #pragma unroll
        for (int ks = 0; ks < 2; ks++) {
            const int kk2 = ks * 8;
            uint32_t af[4], bf[8][2];
            af[0] = As32[wm + g][kk2 + t];
            af[1] = As32[wm + g + 8][kk2 + t];
            af[2] = As32[wm + g][kk2 + t + 4];
            af[3] = As32[wm + g + 8][kk2 + t + 4];
            #pragma unroll
            for (int j = 0; j < 8; j++) {
                const int dc = j * 8 + g;
                bf[j][0] = Bs32[dc][kk2 + t];
                bf[j][1] = Bs32[dc][kk2 + t + 4];
            }
            #pragma unroll
            for (int j = 0; j < 8; j++)
                mma_f16(acc[j], af, bf[j]);
        }
        __syncthreads();
    }

    const int r0 = ob * 128 + wm + g;
    const int r1 = r0 + 8;
    #pragma unroll
    for (int j = 0; j < 8; j++) {
        const int dc = j * 8 + 2 * t;
        *(float2*)(fold + ((size_t)b * NC + r0) * HID + h * 64 + dc) =
            make_float2(acc[j][0], acc[j][1]);
        *(float2*)(fold + ((size_t)b * NC + r1) * HID + h * 64 + dc) =
            make_float2(acc[j][2], acc[j][3]);
    }
}

// ---------------- launch ----------------
extern "C" void kernel_launch(void* const* d_in, const int* in_sizes, int n_in,
                              void* d_out, int out_size)
{
    const float* x    = (const float*)d_in[0];
    const float* cin  = (const float*)d_in[1];
    const float* Wq   = (const float*)d_in[2];
    const float* Wk   = (const float*)d_in[3];
    const float* Wv   = (const float*)d_in[4];
    const float* Wo   = (const float*)d_in[5];
    const float* bo   = (const float*)d_in[6];
    float* out = (float*)d_out;

    __half *kh, *wkh, *wqh, *wwh, *tn;
    float *tp, *fd, *cb;
    cudaGetSymbolAddress((void**)&kh, g_kh);
    cudaGetSymbolAddress((void**)&wkh, g_wkh);
    cudaGetSymbolAddress((void**)&wqh, g_wqh);
    cudaGetSymbolAddress((void**)&wwh, g_wwh);
    cudaGetSymbolAddress((void**)&tn, g_Tn);
    cudaGetSymbolAddress((void**)&tp, g_Tpart);
    cudaGetSymbolAddress((void**)&fd, g_fold);
    cudaGetSymbolAddress((void**)&cb, g_comb);

    const float scale = 0.125f;

    pack_w<<<HID * NC / 256, 256>>>(Wk, Wq, wkh, wqh);

    // WW[h] = Wo_h @ Wv_h (half)
    dim3 gww(NHEAD, NC / 16);
    ww_kernel<<<gww, 256>>>(Wo, Wv, wwh);

    // k = exp(Wk @ cin) -> half (M=512, N=4096, K=256 per batch)
    dim3 gproj(NPIX / 128, HID / 128, NB);
    mma_gemm_t<1, 0, 1><<<gproj, 256>>>(wkh, 0, NC, cin, (long)NC * NPIX, NPIX,
                                        kh, (long)HID * NPIX, NPIX, nullptr, NC, 1.0f);

    // T partials: T[d][c] = sum_m expk[d,m]*cin[c,m] (+ row sums)
    dim3 gt(NB * NHEAD, NCHUNK, 2);
    t_partial_kernel<<<gt, 256>>>(kh, cin, tp);

    // reduce + normalize -> Tn (half)
    reduce_t_kernel<<<NB * NHEAD, 256>>>(tp, tn);

    // fold[b][o][h*64+d] = WW[h] @ Tn[bh]^T
    dim3 gfold(NB * NHEAD, 2);
    foldg_kernel<<<gfold, 256>>>(wwh, tn, fd);

    // comb[b] = fold[b] @ (scale*Wq)  (M=256, N=256, K=512)
    dim3 gcomb(NC / 128, NC / 128, NB);
    mma_gemm_t<0, 1, 0><<<gcomb, 256>>>(fd, (long)NC * HID, HID, wqh, 0, NC,
                                        cb, (long)NC * NC, NC, nullptr, HID, scale);

    // out = comb @ x + bo  (M=256, N=4096, K=256)
    dim3 gfin(NPIX / 128, NC / 128, NB);
    mma_gemm_t<0, 0, 0><<<gfin, 256>>>(cb, (long)NC * NC, NC, x, (long)NC * NPIX, NPIX,
                                       out, (long)NC * NPIX, NPIX, bo, NC, 1.0f);
}

// round 16
// speedup vs baseline: 1.0762x; 1.0762x over previous
#include <cuda_runtime.h>
#include <cuda_fp16.h>
#include <math.h>
#include <stdint.h>

#define NB    8
#define NC    256
#define HID   512
#define NPIX  4096
#define NHEAD 8
#define DHEAD 64
#define NCHUNK 8
#define TLD   260                    // 256 data cols + es at 256 + pad
#define TROWS (HID)                  // 512 dk rows per (chunk, batch)

// ---------------- scratch ----------------
__device__ __align__(256) __half g_kh[NB * HID * NPIX];       // exp(k), 33.5 MB
__device__ __align__(256) __half g_wkh[HID * NC];
__device__ __align__(256) __half g_wqh[HID * NC];
__device__ __align__(256) __half g_wwh[NHEAD * NC * NC];      // WW[h] = Wo_h @ Wv_h
__device__ __align__(256) float g_Tpart[NCHUNK * NB * TROWS * TLD];  // 34 MB
__device__ __align__(256) __half g_Tn[NB * NHEAD * DHEAD * NC];      // normalized T, half
__device__ __align__(256) float g_fold[NB * NC * HID];
__device__ __align__(256) float g_comb[NB * NC * NC];

// ---------------- helpers ----------------
__device__ __forceinline__ void mma_f16(float* d, const uint32_t* a, const uint32_t* b) {
    asm volatile(
        "mma.sync.aligned.m16n8k16.row.col.f32.f16.f16.f32 "
        "{%0,%1,%2,%3}, {%4,%5,%6,%7}, {%8,%9}, {%0,%1,%2,%3};"
        : "+f"(d[0]), "+f"(d[1]), "+f"(d[2]), "+f"(d[3])
        : "r"(a[0]), "r"(a[1]), "r"(a[2]), "r"(a[3]), "r"(b[0]), "r"(b[1]));
}

// ---------------- pack weights to half: Wk, Wq ----------------
__global__ void pack_w(const float* __restrict__ Wk, const float* __restrict__ Wq,
                       __half* __restrict__ Wkh, __half* __restrict__ Wqh)
{
    const int i = blockIdx.x * 256 + threadIdx.x;
    Wkh[i] = __float2half_rn(Wk[i]);
    Wqh[i] = __float2half_rn(Wq[i]);
}

// ---------------- WW[h][o][c] = sum_e Wo[o][h*64+e] * Wv[h*64+e][c] ----------------
__global__ void ww_kernel(const float* __restrict__ Wo, const float* __restrict__ Wv,
                          __half* __restrict__ WWh)
{
    const int h = blockIdx.x;
    const int ob = blockIdx.y;
    __shared__ float wo_s[16][64];

    const int tid = threadIdx.x;
    for (int i = tid; i < 1024; i += 256) {
        const int o = i >> 6, e = i & 63;
        wo_s[o][e] = Wo[(size_t)(ob * 16 + o) * HID + h * 64 + e];
    }
    __syncthreads();

    const int c = tid;
    #pragma unroll 1
    for (int o = 0; o < 16; o++) {
        float s = 0.0f;
        #pragma unroll
        for (int e = 0; e < 64; e++)
            s += wo_s[o][e] * Wv[(size_t)(h * 64 + e) * NC + c];
        WWh[(size_t)h * NC * NC + (size_t)(ob * 16 + o) * NC + c] = __float2half_rn(s);
    }
}

// ---------------- fp16 mma GEMM (R8-proven), MODE 1 => half C with exp ----------------
template<int AHALF, int BHALF, int MODE>
__global__ __launch_bounds__(256, 2)
void mma_gemm_t(const void* __restrict__ Av, long sA, int lda,
                const void* __restrict__ Bv, long sB, int ldb,
                void* __restrict__ Cv, long sC, int ldc,
                const float* __restrict__ bias, int K, float alpha)
{
    __shared__ uint32_t As32[2][128][20];
    __shared__ uint32_t Bs32[2][16][136];

    const int bb = blockIdx.z;
    const float*  Af = (const float*)Av + (AHALF ? 0 : (size_t)bb * sA);
    const __half* Ah = (const __half*)Av + (AHALF ? (size_t)bb * sA : 0);
    const float*  Bf = (const float*)Bv + (BHALF ? 0 : (size_t)bb * sB);
    const __half* Bh = (const __half*)Bv + (BHALF ? (size_t)bb * sB : 0);

    const int tid = threadIdx.x;
    const int wid = tid >> 5, lid = tid & 31;
    const int g = lid >> 2, t = lid & 3;
    const int wm = (wid >> 2) * 64, wn = (wid & 3) * 32;
    const int m0 = blockIdx.y * 128, n0 = blockIdx.x * 128;

    const int am = tid >> 1;
    const int as = tid & 1;
    const int bk = tid >> 3;
    const int bn8 = (tid & 7) * 16;

    float acc[4][4][4];
    #pragma unroll
    for (int i = 0; i < 4; i++)
        #pragma unroll
        for (int j = 0; j < 4; j++)
            #pragma unroll
            for (int q = 0; q < 4; q++) acc[i][j][q] = 0.0f;

    const int KT = K >> 5;

    float4 aRf[4];
    uint4  aRh0, aRh1;
    float4 bRf[4];
    uint4  bRh0, bRh1;

    auto loadA = [&](int k0) {
        if (AHALF) {
            const __half* ap = Ah + (size_t)(m0 + am) * lda + k0 + as * 16;
            aRh0 = *(const uint4*)(ap);
            aRh1 = *(const uint4*)(ap + 8);
        } else {
            const float* ap = Af + (size_t)(m0 + am) * lda + k0;
            #pragma unroll
            for (int p = 0; p < 4; p++)
                aRf[p] = *(const float4*)(ap + (as + 2 * p) * 4);
        }
    };
    auto loadB = [&](int k0) {
        if (BHALF) {
            const __half* bp = Bh + (size_t)(k0 + bk) * ldb + n0 + bn8;
            bRh0 = *(const uint4*)(bp);
            bRh1 = *(const uint4*)(bp + 8);
        } else {
            const float* bp = Bf + (size_t)(k0 + bk) * ldb + n0 + bn8;
            #pragma unroll
            for (int p = 0; p < 4; p++)
                bRf[p] = *(const float4*)(bp + 4 * p);
        }
    };
    auto storeA = [&](int buf) {
        if (AHALF) {
            const int k2 = as * 8;
            As32[buf][am][k2 + 0] = aRh0.x; As32[buf][am][k2 + 1] = aRh0.y;
            As32[buf][am][k2 + 2] = aRh0.z; As32[buf][am][k2 + 3] = aRh0.w;
            As32[buf][am][k2 + 4] = aRh1.x; As32[buf][am][k2 + 5] = aRh1.y;
            As32[buf][am][k2 + 6] = aRh1.z; As32[buf][am][k2 + 7] = aRh1.w;
        } else {
            #pragma unroll
            for (int p = 0; p < 4; p++) {
                const int k2 = (as + 2 * p) * 2;
                __half2 h0 = __floats2half2_rn(aRf[p].x, aRf[p].y);
                __half2 h1 = __floats2half2_rn(aRf[p].z, aRf[p].w);
                As32[buf][am][k2 + 0] = *(uint32_t*)&h0;
                As32[buf][am][k2 + 1] = *(uint32_t*)&h1;
            }
        }
    };
    auto storeB = [&](int buf) {
        __half* bsh = (__half*)&Bs32[buf][0][0];
        const int base = (bk >> 1) * 272 + (bk & 1);
        if (BHALF) {
            const uint32_t w[8] = {bRh0.x, bRh0.y, bRh0.z, bRh0.w, bRh1.x, bRh1.y, bRh1.z, bRh1.w};
            #pragma unroll
            for (int q = 0; q < 8; q++) {
                __half2 h = *(__half2*)&w[q];
                bsh[base + 2 * (bn8 + 2 * q + 0)] = __low2half(h);
                bsh[base + 2 * (bn8 + 2 * q + 1)] = __high2half(h);
            }
        } else {
            #pragma unroll
            for (int p = 0; p < 4; p++) {
                const int nf = bn8 + 4 * p;
                bsh[base + 2 * (nf + 0)] = __float2half_rn(bRf[p].x);
                bsh[base + 2 * (nf + 1)] = __float2half_rn(bRf[p].y);
                bsh[base + 2 * (nf + 2)] = __float2half_rn(bRf[p].z);
                bsh[base + 2 * (nf + 3)] = __float2half_rn(bRf[p].w);
            }
        }
    };

    loadA(0);
    loadB(0);
    storeA(0);
    storeB(0);
    __syncthreads();

    for (int kt = 0; kt < KT; kt++) {
        const int cur = kt & 1;
        const int nxt = cur ^ 1;
        const bool more = (kt + 1 < KT);

        if (more) {
            loadA((kt + 1) << 5);
            loadB((kt + 1) << 5);
        }

        #pragma unroll
        for (int ks = 0; ks < 2; ks++) {
            const int kk2 = ks * 8;
            uint32_t af[4][4], bf[4][2];
            #pragma unroll
            for (int i = 0; i < 4; i++) {
                const int r = wm + i * 16 + g;
                af[i][0] = As32[cur][r][kk2 + t];
                af[i][1] = As32[cur][r + 8][kk2 + t];
                af[i][2] = As32[cur][r][kk2 + t + 4];
                af[i][3] = As32[cur][r + 8][kk2 + t + 4];
            }
            #pragma unroll
            for (int j = 0; j < 4; j++) {
                const int c = wn + j * 8 + g;
                bf[j][0] = Bs32[cur][kk2 + t][c];
                bf[j][1] = Bs32[cur][kk2 + t + 4][c];
            }
            #pragma unroll
            for (int i = 0; i < 4; i++)
                #pragma unroll
                for (int j = 0; j < 4; j++)
                    mma_f16(acc[i][j], af[i], bf[j]);
        }

        if (more) {
            storeA(nxt);
            storeB(nxt);
        }
        __syncthreads();
    }

    if (MODE == 0) {
        float* C = (float*)Cv + (size_t)bb * sC;
        #pragma unroll
        for (int i = 0; i < 4; i++) {
            const int r0 = m0 + wm + i * 16 + g;
            const int r1 = r0 + 8;
            const float bi0 = bias ? bias[r0] : 0.0f;
            const float bi1 = bias ? bias[r1] : 0.0f;
            #pragma unroll
            for (int j = 0; j < 4; j++) {
                const int col = n0 + wn + j * 8 + 2 * t;
                float2 o0 = make_float2(acc[i][j][0] * alpha + bi0, acc[i][j][1] * alpha + bi0);
                float2 o1 = make_float2(acc[i][j][2] * alpha + bi1, acc[i][j][3] * alpha + bi1);
                *(float2*)(C + (size_t)r0 * ldc + col) = o0;
                *(float2*)(C + (size_t)r1 * ldc + col) = o1;
            }
        }
    } else {
        __half* C = (__half*)Cv + (size_t)bb * sC;
        #pragma unroll
        for (int i = 0; i < 4; i++) {
            const int r0 = m0 + wm + i * 16 + g;
            const int r1 = r0 + 8;
            #pragma unroll
            for (int j = 0; j < 4; j++) {
                const int col = n0 + wn + j * 8 + 2 * t;
                float4 v = make_float4(expf(acc[i][j][0]), expf(acc[i][j][1]),
                                       expf(acc[i][j][2]), expf(acc[i][j][3]));
                *(__half2*)(C + (size_t)r0 * ldc + col) = __floats2half2_rn(v.x, v.y);
                *(__half2*)(C + (size_t)r1 * ldc + col) = __floats2half2_rn(v.z, v.w);
            }
        }
    }
}

// ---------------- T GEMM (per-batch, all heads): NT, tile 128x128x32, double-buffered ----------------
// T[dk][c] = sum_m expk[dk,m] * cin[c,m].  grid (4 dk-tiles, 2 c-tiles, NB*NCHUNK).
// es row sums (sum_m expk[dk,m]) written by c-tile 0 at col 256.
__global__ __launch_bounds__(256, 2)
void t_gemm_kernel(const __half* __restrict__ Kh, const float* __restrict__ cin,
                   float* __restrict__ part)
{
    __shared__ uint32_t As32[2][128][20];   // expk [dk][m2]
    __shared__ uint32_t Bs32[2][128][20];   // cin->half [c][m2]

    const int mt = blockIdx.x;              // dk tile 0..3
    const int ct = blockIdx.y;              // c tile 0..1
    const int b  = blockIdx.z >> 3;
    const int ch = blockIdx.z & 7;

    const __half* A  = Kh + (size_t)b * HID * NPIX + (size_t)(mt * 128) * NPIX;
    const float*  Bp = cin + (size_t)b * NC * NPIX + (size_t)(ct * 128) * NPIX;
    const int mbeg = ch * (NPIX / NCHUNK);  // 512 m per chunk

    const int tid = threadIdx.x;
    const int wid = tid >> 5, lid = tid & 31;
    const int g = lid >> 2, t = lid & 3;
    const int wm = (wid >> 2) * 64, wn = (wid & 3) * 32;

    const int row = tid >> 1;               // loader row 0..127 (for both A and B)
    const int hs  = tid & 1;                // m-half selector

    float acc[4][4][4];
    #pragma unroll
    for (int i = 0; i < 4; i++)
        #pragma unroll
        for (int j = 0; j < 4; j++)
            #pragma unroll
            for (int q = 0; q < 4; q++) acc[i][j][q] = 0.0f;

    float es = 0.0f;
    uint4 aR0, aR1;
    float4 bRf[4];

    auto loadA = [&](int m0) {
        const __half* ap = A + (size_t)row * NPIX + m0 + hs * 16;
        aR0 = *(const uint4*)(ap);
        aR1 = *(const uint4*)(ap + 8);
        if (ct == 0) {
            const uint32_t w[8] = {aR0.x, aR0.y, aR0.z, aR0.w, aR1.x, aR1.y, aR1.z, aR1.w};
            #pragma unroll
            for (int q = 0; q < 8; q++) {
                float2 f = __half22float2(*(__half2*)&w[q]);
                es += f.x + f.y;
            }
        }
    };
    auto loadB = [&](int m0) {
        const float* bp = Bp + (size_t)row * NPIX + m0 + hs * 16;
        #pragma unroll
        for (int p = 0; p < 4; p++)
            bRf[p] = *(const float4*)(bp + 4 * p);
    };
    auto storeA = [&](int buf) {
        const int k2 = hs * 8;
        As32[buf][row][k2 + 0] = aR0.x; As32[buf][row][k2 + 1] = aR0.y;
        As32[buf][row][k2 + 2] = aR0.z; As32[buf][row][k2 + 3] = aR0.w;
        As32[buf][row][k2 + 4] = aR1.x; As32[buf][row][k2 + 5] = aR1.y;
        As32[buf][row][k2 + 6] = aR1.z; As32[buf][row][k2 + 7] = aR1.w;
    };
    auto storeB = [&](int buf) {
        const int k2 = hs * 8;
        #pragma unroll
        for (int p = 0; p < 4; p++) {
            __half2 h0 = __floats2half2_rn(bRf[p].x, bRf[p].y);
            __half2 h1 = __floats2half2_rn(bRf[p].z, bRf[p].w);
            Bs32[buf][row][k2 + 2 * p + 0] = *(uint32_t*)&h0;
            Bs32[buf][row][k2 + 2 * p + 1] = *(uint32_t*)&h1;
        }
    };

    loadA(mbeg);
    loadB(mbeg);
    storeA(0);
    storeB(0);
    __syncthreads();

    #pragma unroll 1
    for (int kt = 0; kt < 16; kt++) {
        const int cur = kt & 1;
        const int nxt = cur ^ 1;
        const bool more = (kt + 1 < 16);

        if (more) {
            loadA(mbeg + (kt + 1) * 32);
            loadB(mbeg + (kt + 1) * 32);
        }

        #pragma unroll
        for (int ks = 0; ks < 2; ks++) {
            const int kk2 = ks * 8;
            uint32_t af[4][4], bf[4][2];
            #pragma unroll
            for (int i = 0; i < 4; i++) {
                const int r = wm + i * 16 + g;
                af[i][0] = As32[cur][r][kk2 + t];
                af[i][1] = As32[cur][r + 8][kk2 + t];
                af[i][2] = As32[cur][r][kk2 + t + 4];
                af[i][3] = As32[cur][r + 8][kk2 + t + 4];
            }
            #pragma unroll
            for (int j = 0; j < 4; j++) {
                const int c = wn + j * 8 + g;
                bf[j][0] = Bs32[cur][c][kk2 + t];
                bf[j][1] = Bs32[cur][c][kk2 + t + 4];
            }
            #pragma unroll
            for (int i = 0; i < 4; i++)
                #pragma unroll
                for (int j = 0; j < 4; j++)
                    mma_f16(acc[i][j], af[i], bf[j]);
        }

        if (more) {
            storeA(nxt);
            storeB(nxt);
        }
        __syncthreads();
    }

    // write partials: row = (ch*NB+b)*512 + mt*128 + ..., col = ct*128 + ...
    float* cp = part + ((size_t)(ch * NB + b) * TROWS + mt * 128) * TLD;
    #pragma unroll
    for (int i = 0; i < 4; i++) {
        const int r0 = wm + i * 16 + g;
        const int r1 = r0 + 8;
        #pragma unroll
        for (int j = 0; j < 4; j++) {
            const int c = ct * 128 + wn + j * 8 + 2 * t;
            *(float2*)(cp + (size_t)r0 * TLD + c) = make_float2(acc[i][j][0], acc[i][j][1]);
            *(float2*)(cp + (size_t)r1 * TLD + c) = make_float2(acc[i][j][2], acc[i][j][3]);
        }
    }

    if (ct == 0) {
        es += __shfl_xor_sync(0xffffffffu, es, 1);
        if (hs == 0) cp[(size_t)row * TLD + 256] = es;
    }
}

// ---------------- reduce T partials + normalize -> Tn (half) ----------------
__global__ void reduce_t_kernel(const float* __restrict__ part, __half* __restrict__ Tn)
{
    const int bh = blockIdx.x;
    const int b = bh >> 3, h = bh & 7;
    const int tid = threadIdx.x;

    __shared__ float Sd[64];
    if (tid < 64) {
        float s = 0.0f;
        #pragma unroll
        for (int ch = 0; ch < NCHUNK; ch++)
            s += part[((size_t)(ch * NB + b) * TROWS + h * 64 + tid) * TLD + 256];
        Sd[tid] = 1.0f / s;
    }
    __syncthreads();

    uint2* outp = (uint2*)(Tn + (size_t)bh * DHEAD * NC);
    #pragma unroll 1
    for (int it = 0; it < 16; it++) {
        const int slot = it * 256 + tid;
        const int dd = slot >> 6, c4 = (slot & 63) << 2;
        float4 s = make_float4(0.f, 0.f, 0.f, 0.f);
        #pragma unroll
        for (int ch = 0; ch < NCHUNK; ch++) {
            float4 p = *(const float4*)(part +
                ((size_t)(ch * NB + b) * TROWS + h * 64 + dd) * TLD + c4);
            s.x += p.x; s.y += p.y; s.z += p.z; s.w += p.w;
        }
        const float iv = Sd[dd];
        __half2 h0 = __floats2half2_rn(s.x * iv, s.y * iv);
        __half2 h1 = __floats2half2_rn(s.z * iv, s.w * iv);
        uint2 u;
        u.x = *(uint32_t*)&h0;
        u.y = *(uint32_t*)&h1;
        outp[slot] = u;
    }
}

// ---------------- foldg: fold[b][o][h*64+d] = sum_c WW[h][o][c] * Tn[bh][d][c] ----------------
__global__ __launch_bounds__(256)
void foldg_kernel(const __half* __restrict__ WWh, const __half* __restrict__ Tn,
                  float* __restrict__ fold)
{
    const int bh = blockIdx.x;
    const int ob = blockIdx.y;
    const int b = bh >> 3, h = bh & 7;
    const __half* A = WWh + (size_t)h * NC * NC + (size_t)ob * 128 * NC;
    const __half* B = Tn + (size_t)bh * DHEAD * NC;

    __shared__ uint32_t As32[128][20];
    __shared__ uint32_t Bs32[64][20];

    const int tid = threadIdx.x;
    const int wid = tid >> 5, lid = tid & 31;
    const int g = lid >> 2, t = lid & 3;
    const int wm = wid * 16;

    const int ar = tid >> 1, ac16 = (tid & 1) * 16;
    const int br = tid >> 2, bm8 = (tid & 3) << 3;

    float acc[8][4];
    #pragma unroll
    for (int j = 0; j < 8; j++)
        #pragma unroll
        for (int q = 0; q < 4; q++) acc[j][q] = 0.0f;

    for (int k0 = 0; k0 < NC; k0 += 32) {
        uint4 a0 = *(const uint4*)(A + (size_t)ar * NC + k0 + ac16);
        uint4 a1 = *(const uint4*)(A + (size_t)ar * NC + k0 + ac16 + 8);
        const int aw = (tid & 1) * 8;
        As32[ar][aw + 0] = a0.x; As32[ar][aw + 1] = a0.y;
        As32[ar][aw + 2] = a0.z; As32[ar][aw + 3] = a0.w;
        As32[ar][aw + 4] = a1.x; As32[ar][aw + 5] = a1.y;
        As32[ar][aw + 6] = a1.z; As32[ar][aw + 7] = a1.w;
        uint4 bv = *(const uint4*)(B + (size_t)br * NC + k0 + bm8);
        const int bw = bm8 >> 1;
        Bs32[br][bw + 0] = bv.x; Bs32[br][bw + 1] = bv.y;
        Bs32[br][bw + 2] = bv.z; Bs32[br][bw + 3] = bv.w;
        __syncthreads();

        #pragma unroll
        for (int ks = 0; ks < 2; ks++) {
            const int kk2 = ks * 8;
            uint32_t af[4], bf[8][2];
            af[0] = As32[wm + g][kk2 + t];
            af[1] = As32[wm + g + 8][kk2 + t];
            af[2] = As32[wm + g][kk2 + t + 4];
            af[3] = As32[wm + g + 8][kk2 + t + 4];
            #pragma unroll
            for (int j = 0; j < 8; j++) {
                const int dc = j * 8 + g;
                bf[j][0] = Bs32[dc][kk2 + t];
                bf[j][1] = Bs32[dc][kk2 + t + 4];
            }
            #pragma unroll
            for (int j = 0; j < 8; j++)
                mma_f16(acc[j], af, bf[j]);
        }
        __syncthreads();
    }

    const int r0 = ob * 128 + wm + g;
    const int r1 = r0 + 8;
    #pragma unroll
    for (int j = 0; j < 8; j++) {
        const int dc = j * 8 + 2 * t;
        *(float2*)(fold + ((size_t)b * NC + r0) * HID + h * 64 + dc) =
            make_float2(acc[j][0], acc[j][1]);
        *(float2*)(fold + ((size_t)b * NC + r1) * HID + h * 64 + dc) =
            make_float2(acc[j][2], acc[j][3]);
    }
}

// ---------------- launch ----------------
extern "C" void kernel_launch(void* const* d_in, const int* in_sizes, int n_in,
                              void* d_out, int out_size)
{
    const float* x    = (const float*)d_in[0];
    const float* cin  = (const float*)d_in[1];
    const float* Wq   = (const float*)d_in[2];
    const float* Wk   = (const float*)d_in[3];
    const float* Wv   = (const float*)d_in[4];
    const float* Wo   = (const float*)d_in[5];
    const float* bo   = (const float*)d_in[6];
    float* out = (float*)d_out;

    __half *kh, *wkh, *wqh, *wwh, *tn;
    float *tp, *fd, *cb;
    cudaGetSymbolAddress((void**)&kh, g_kh);
    cudaGetSymbolAddress((void**)&wkh, g_wkh);
    cudaGetSymbolAddress((void**)&wqh, g_wqh);
    cudaGetSymbolAddress((void**)&wwh, g_wwh);
    cudaGetSymbolAddress((void**)&tn, g_Tn);
    cudaGetSymbolAddress((void**)&tp, g_Tpart);
    cudaGetSymbolAddress((void**)&fd, g_fold);
    cudaGetSymbolAddress((void**)&cb, g_comb);

    const float scale = 0.125f;

    pack_w<<<HID * NC / 256, 256>>>(Wk, Wq, wkh, wqh);

    // WW[h] = Wo_h @ Wv_h (half)
    dim3 gww(NHEAD, NC / 16);
    ww_kernel<<<gww, 256>>>(Wo, Wv, wwh);

    // k = exp(Wk @ cin) -> half (M=512, N=4096, K=256 per batch)
    dim3 gproj(NPIX / 128, HID / 128, NB);
    mma_gemm_t<1, 0, 1><<<gproj, 256>>>(wkh, 0, NC, cin, (long)NC * NPIX, NPIX,
                                        kh, (long)HID * NPIX, NPIX, nullptr, NC, 1.0f);

    // T partials: per-batch NT GEMM over all heads (+ es row sums)
    dim3 gt(4, 2, NB * NCHUNK);
    t_gemm_kernel<<<gt, 256>>>(kh, cin, tp);

    // reduce + normalize -> Tn (half)
    reduce_t_kernel<<<NB * NHEAD, 256>>>(tp, tn);

    // fold[b][o][h*64+d] = WW[h] @ Tn[bh]^T
    dim3 gfold(NB * NHEAD, 2);
    foldg_kernel<<<gfold, 256>>>(wwh, tn, fd);

    // comb[b] = fold[b] @ (scale*Wq)  (M=256, N=256, K=512)
    dim3 gcomb(NC / 128, NC / 128, NB);
    mma_gemm_t<0, 1, 0><<<gcomb, 256>>>(fd, (long)NC * HID, HID, wqh, 0, NC,
                                        cb, (long)NC * NC, NC, nullptr, HID, scale);

    // out = comb @ x + bo  (M=256, N=4096, K=256)
    dim3 gfin(NPIX / 128, NC / 128, NB);
    mma_gemm_t<0, 0, 0><<<gfin, 256>>>(cb, (long)NC * NC, NC, x, (long)NC * NPIX, NPIX,
                                       out, (long)NC * NPIX, NPIX, bo, NC, 1.0f);
}